// round 2
// baseline (speedup 1.0000x reference)
#include <cuda_runtime.h>
#include <math.h>

#define H    850
#define H2   1700
#define BB   256
#define TT   128
#define BH   (BB*H)
#define WSZ  (H*H)

__device__ float g_W0x[H*H2];
__device__ float g_W0hc[WSZ];
__device__ float g_W0hh[WSZ];
__device__ float g_Wc[8*WSZ];
__device__ float g_Wh[8*WSZ];
__device__ float g_XW[(size_t)TT*BB*H2];
__device__ float g_S[9][BH];

__device__ __forceinline__ unsigned long long pack2(float x, float y) {
    unsigned long long r;
    asm("mov.b64 %0, {%1, %2};" : "=l"(r) : "f"(x), "f"(y));
    return r;
}
__device__ __forceinline__ void fma2(unsigned long long& d,
                                     unsigned long long a, unsigned long long b) {
    asm("fma.rn.f32x2 %0, %1, %2, %0;" : "+l"(d) : "l"(a), "l"(b));
}
__device__ __forceinline__ float2 unpack2(unsigned long long v) {
    float2 f;
    asm("mov.b64 {%0, %1}, %2;" : "=f"(f.x), "=f"(f.y) : "l"(v));
    return f;
}

#define ACT_TANH 0
#define ACT_RELU 1
#define ACT_SIG  2
#define ACT_ID   3

__device__ __forceinline__ float apply_act(float x, int a) {
    switch (a) {
        case ACT_TANH: return tanhf(x);
        case ACT_RELU: return fmaxf(x, 0.f);
        case ACT_SIG:  return 1.f / (1.f + expf(-x));
        default:       return x;
    }
}

// ---- precompute GEMM: C[M,N] = (A .* sig_k) @ B ----
// mode 0: fuse W0 (scatter to g_W0x/g_W0hc/g_W0hh)
// mode 1: fuse Ws[z] (scatter to g_Wc[z]/g_Wh[z])
// mode 2: XW = X @ g_W0x  -> g_XW
__device__ __forceinline__ void store_pre(int mode, int z, int m, int n, float v) {
    if (mode == 0) {
        if (m < H)      g_W0x[m*H2 + n] = v;
        else if (n < H) g_W0hc[(m-H)*H + n] = v;
        else            g_W0hh[(m-H)*H + (n-H)] = v;
    } else if (mode == 1) {
        if (n < H) g_Wc[(size_t)z*WSZ + m*H + n] = v;
        else       g_Wh[(size_t)z*WSZ + m*H + (n-H)] = v;
    } else {
        g_XW[(size_t)m*H2 + n] = v;
    }
}

__global__ void __launch_bounds__(256,2) gemm_pre(
    int mode, const float* __restrict__ A, const float* __restrict__ Sig,
    const float* __restrict__ Bx, int M, int N, int K, int lda, int ldb)
{
    __shared__ __align__(16) float As[16][136];
    __shared__ __align__(16) float Bs[16][128];

    int z = blockIdx.z;
    const float* Ap = A;
    const float* Bp = Bx;
    const float* Sp = Sig;
    if (mode == 1) { Ap = A + (size_t)z*WSZ; Sp = Sig + z*H; Bp = Bx + (size_t)z*H2*H2; }
    else if (mode == 2) { Bp = g_W0x; }

    int tid = threadIdx.x;
    int tx = tid & 15, ty = tid >> 4;
    int m0 = blockIdx.y << 7, n0 = blockIdx.x << 7;

    unsigned long long acc[8][4];
    #pragma unroll
    for (int i = 0; i < 8; i++)
        #pragma unroll
        for (int j = 0; j < 4; j++) acc[i][j] = 0ull;

    for (int kt = 0; kt < K; kt += 16) {
        #pragma unroll
        for (int i = 0; i < 8; i++) {
            int idx = tid + (i << 8);
            int ak = idx & 15, am = idx >> 4;
            int gm = m0 + am, gk = kt + ak;
            float v = 0.f;
            if (gm < M && gk < K) {
                v = Ap[(size_t)gm*lda + gk];
                if (Sp) v *= Sp[gk];
            }
            As[ak][am] = v;
        }
        #pragma unroll
        for (int i = 0; i < 8; i++) {
            int idx = tid + (i << 8);
            int bk = idx >> 7, bn = idx & 127;
            int gk = kt + bk, gn = n0 + bn;
            Bs[bk][bn] = (gk < K && gn < N) ? Bp[(size_t)gk*ldb + gn] : 0.f;
        }
        __syncthreads();
        #pragma unroll
        for (int kk = 0; kk < 16; kk++) {
            float4 a0 = *(const float4*)&As[kk][ty*8];
            float4 a1 = *(const float4*)&As[kk][ty*8+4];
            ulonglong2 b0 = *(const ulonglong2*)&Bs[kk][tx*8];
            ulonglong2 b1 = *(const ulonglong2*)&Bs[kk][tx*8+4];
            float av[8] = {a0.x,a0.y,a0.z,a0.w,a1.x,a1.y,a1.z,a1.w};
            unsigned long long bv[4] = {b0.x,b0.y,b1.x,b1.y};
            #pragma unroll
            for (int mm = 0; mm < 8; mm++) {
                unsigned long long ap = pack2(av[mm], av[mm]);
                #pragma unroll
                for (int np = 0; np < 4; np++) fma2(acc[mm][np], ap, bv[np]);
            }
        }
        __syncthreads();
    }

    #pragma unroll
    for (int mm = 0; mm < 8; mm++) {
        int gm = m0 + ty*8 + mm;
        if (gm >= M) continue;
        #pragma unroll
        for (int np = 0; np < 4; np++) {
            float2 v = unpack2(acc[mm][np]);
            int gn = n0 + tx*8 + np*2;
            if (gn   < N) store_pre(mode, z, gm, gn,   v.x);
            if (gn+1 < N) store_pre(mode, z, gm, gn+1, v.y);
        }
    }
}

// ---- fused recurrent step: out = sp + sigmoid(c)*(act(h) - sp) ----
#define SBM 32
#define SBN 64
#define SBK 16

struct StepD { int a_sel, w, o_sel, act; };
struct LevelArgs { StepD s[3]; const float* hprev; int bias_t; };

__global__ void __launch_bounds__(128) step_kernel(LevelArgs la)
{
    __shared__ __align__(16) float As[SBK][36];
    __shared__ __align__(16) float Bcs[SBK][SBN];
    __shared__ __align__(16) float Bhs[SBK][SBN];

    StepD sd = la.s[blockIdx.z];
    const float* A  = (sd.a_sel < 0) ? la.hprev : g_S[sd.a_sel];
    const float* Wc = (sd.w < 0) ? g_W0hc : (g_Wc + (size_t)sd.w*WSZ);
    const float* Wh = (sd.w < 0) ? g_W0hh : (g_Wh + (size_t)sd.w*WSZ);
    float* O = g_S[sd.o_sel];

    int tid = threadIdx.x;
    int tx = tid & 15, ty = tid >> 4;
    int m0 = blockIdx.y * SBM;
    int n0 = blockIdx.x * SBN;

    unsigned long long accC[4][2], accH[4][2];
    #pragma unroll
    for (int i = 0; i < 4; i++) {
        accC[i][0] = accC[i][1] = 0ull;
        accH[i][0] = accH[i][1] = 0ull;
    }

    for (int kt = 0; kt < H; kt += SBK) {
        #pragma unroll
        for (int i = 0; i < 4; i++) {
            int idx = tid + (i << 7);
            int ak = idx & 15, am = idx >> 4;
            int gk = kt + ak;
            As[ak][am] = (gk < H) ? A[(m0 + am)*H + gk] : 0.f;
        }
        #pragma unroll
        for (int i = 0; i < 8; i++) {
            int idx = tid + (i << 7);
            int bk = idx >> 6, bn = idx & 63;
            int gk = kt + bk, gn = n0 + bn;
            float vc = 0.f, vh = 0.f;
            if (gk < H && gn < H) { vc = Wc[gk*H + gn]; vh = Wh[gk*H + gn]; }
            Bcs[bk][bn] = vc; Bhs[bk][bn] = vh;
        }
        __syncthreads();
        #pragma unroll
        for (int kk = 0; kk < SBK; kk++) {
            float4 a = *(const float4*)&As[kk][ty*4];
            ulonglong2 bc = *(const ulonglong2*)&Bcs[kk][tx*4];
            ulonglong2 bh = *(const ulonglong2*)&Bhs[kk][tx*4];
            unsigned long long ap[4] = {pack2(a.x,a.x), pack2(a.y,a.y),
                                        pack2(a.z,a.z), pack2(a.w,a.w)};
            #pragma unroll
            for (int mm = 0; mm < 4; mm++) {
                fma2(accC[mm][0], ap[mm], bc.x);
                fma2(accC[mm][1], ap[mm], bc.y);
                fma2(accH[mm][0], ap[mm], bh.x);
                fma2(accH[mm][1], ap[mm], bh.y);
            }
        }
        __syncthreads();
    }

    const float* bias = (la.bias_t >= 0) ? (g_XW + (size_t)la.bias_t*BB*H2) : nullptr;
    #pragma unroll
    for (int mm = 0; mm < 4; mm++) {
        int b = m0 + ty*4 + mm;
        #pragma unroll
        for (int np = 0; np < 2; np++) {
            float2 c2 = unpack2(accC[mm][np]);
            float2 h2 = unpack2(accH[mm][np]);
            float cv[2] = {c2.x, c2.y}, hv[2] = {h2.x, h2.y};
            #pragma unroll
            for (int q = 0; q < 2; q++) {
                int n = n0 + tx*4 + np*2 + q;
                if (n < H) {
                    float c  = cv[q], hh = hv[q];
                    if (bias) {
                        c  += bias[(size_t)b*H2 + n];
                        hh += bias[(size_t)b*H2 + H + n];
                    }
                    float sp   = A[b*H + n];
                    float gate = 1.f / (1.f + expf(-c));
                    hh = apply_act(hh, sd.act);
                    O[b*H + n] = sp + gate * (hh - sp);
                }
            }
        }
    }
}

__global__ void mean_kernel(float* __restrict__ out, float* __restrict__ out2)
{
    int i = blockIdx.x * 256 + threadIdx.x;
    if (i < BH) {
        float s = g_S[1][i] + g_S[2][i] + g_S[3][i] + g_S[4][i]
                + g_S[5][i] + g_S[6][i] + g_S[7][i] + g_S[8][i];
        s *= 0.125f;
        out[i] = s;
        if (out2) out2[i] = s;
    }
}

extern "C" void kernel_launch(void* const* d_in, const int* in_sizes, int n_in,
                              void* d_out, int out_size) {
    const float* X   = (const float*)d_in[0];
    const float* h0  = (const float*)d_in[1];
    const float* W0U = (const float*)d_in[2];
    const float* W0s = (const float*)d_in[3];
    const float* W0V = (const float*)d_in[4];
    const float* WsU = (const float*)d_in[5];
    const float* Wss = (const float*)d_in[6];
    const float* WsV = (const float*)d_in[7];
    float* out = (float*)d_out;

    dim3 thr(256);
    gemm_pre<<<dim3(14,14,1),  thr>>>(0, W0U, W0s, W0V, H2, H2, H2, H2, H2);
    gemm_pre<<<dim3(14,7,8),   thr>>>(1, WsU, Wss, WsV, H,  H2, H,  H,  H2);
    gemm_pre<<<dim3(14,256,1), thr>>>(2, X, nullptr, nullptr, TT*BB, H2, H, H, H2);

    dim3 sthr(128);
    for (int t = 0; t < TT; t++) {
        LevelArgs L;
        L.hprev = (t == 0) ? h0 : out + (size_t)(t-1)*BH;
        L.bias_t = t;
        L.s[0] = {-1,-1,0,ACT_TANH};
        step_kernel<<<dim3(14,8,1), sthr>>>(L);
        L.bias_t = -1;
        L.s[0] = {0,0,1,ACT_SIG};
        step_kernel<<<dim3(14,8,1), sthr>>>(L);
        L.s[0] = {1,1,2,ACT_RELU}; L.s[1] = {1,2,3,ACT_RELU}; L.s[2] = {1,3,4,ACT_ID};
        step_kernel<<<dim3(14,8,3), sthr>>>(L);
        L.s[0] = {2,4,5,ACT_TANH}; L.s[1] = {3,6,7,ACT_TANH};
        step_kernel<<<dim3(14,8,2), sthr>>>(L);
        L.s[0] = {5,5,6,ACT_SIG};  L.s[1] = {5,7,8,ACT_RELU};
        step_kernel<<<dim3(14,8,2), sthr>>>(L);
        float* o2 = (t == TT-1) ? (out + (size_t)TT*BH) : nullptr;
        mean_kernel<<<dim3((BH+255)/256), thr>>>(out + (size_t)t*BH, o2);
    }
}

// round 3
// speedup vs baseline: 1.4966x; 1.4966x over previous
#include <cuda_runtime.h>
#include <math.h>

#define H    850
#define H2   1700
#define BB   256
#define TT   128
#define BH   (BB*H)
#define WSZ  (H*H)

__device__ float g_W0x[H*H2];
__device__ float g_W0hc[WSZ];
__device__ float g_W0hh[WSZ];
__device__ float g_Wc[8*WSZ];
__device__ float g_Wh[8*WSZ];
__device__ float g_XW[(size_t)TT*BB*H2];
__device__ float g_S[9][BH];

__device__ __forceinline__ unsigned long long pack2(float x, float y) {
    unsigned long long r;
    asm("mov.b64 %0, {%1, %2};" : "=l"(r) : "f"(x), "f"(y));
    return r;
}
__device__ __forceinline__ void fma2(unsigned long long& d,
                                     unsigned long long a, unsigned long long b) {
    asm("fma.rn.f32x2 %0, %1, %2, %0;" : "+l"(d) : "l"(a), "l"(b));
}
__device__ __forceinline__ float2 unpack2(unsigned long long v) {
    float2 f;
    asm("mov.b64 {%0, %1}, %2;" : "=f"(f.x), "=f"(f.y) : "l"(v));
    return f;
}
__device__ __forceinline__ unsigned tf32(float x) {
    unsigned r;
    asm("cvt.rna.tf32.f32 %0, %1;" : "=r"(r) : "f"(x));
    return r;
}
__device__ __forceinline__ void mma8(float* d, const unsigned* a, const unsigned* b) {
    asm("mma.sync.aligned.m16n8k8.row.col.f32.tf32.tf32.f32 "
        "{%0,%1,%2,%3}, {%4,%5,%6,%7}, {%8,%9}, {%0,%1,%2,%3};"
        : "+f"(d[0]), "+f"(d[1]), "+f"(d[2]), "+f"(d[3])
        : "r"(a[0]), "r"(a[1]), "r"(a[2]), "r"(a[3]), "r"(b[0]), "r"(b[1]));
}

#define ACT_TANH 0
#define ACT_RELU 1
#define ACT_SIG  2
#define ACT_ID   3

__device__ __forceinline__ float apply_act(float x, int a) {
    switch (a) {
        case ACT_TANH: return tanhf(x);
        case ACT_RELU: return fmaxf(x, 0.f);
        case ACT_SIG:  return 1.f / (1.f + expf(-x));
        default:       return x;
    }
}

// ---- fp32 precompute GEMM (weight fusion only) ----
__device__ __forceinline__ void store_pre(int mode, int z, int m, int n, float v) {
    if (mode == 0) {
        if (m < H)      g_W0x[m*H2 + n] = v;
        else if (n < H) g_W0hc[(m-H)*H + n] = v;
        else            g_W0hh[(m-H)*H + (n-H)] = v;
    } else {
        if (n < H) g_Wc[(size_t)z*WSZ + m*H + n] = v;
        else       g_Wh[(size_t)z*WSZ + m*H + (n-H)] = v;
    }
}

__global__ void __launch_bounds__(256,2) gemm_pre(
    int mode, const float* __restrict__ A, const float* __restrict__ Sig,
    const float* __restrict__ Bx, int M, int N, int K, int lda, int ldb)
{
    __shared__ __align__(16) float As[16][136];
    __shared__ __align__(16) float Bs[16][128];

    int z = blockIdx.z;
    const float* Ap = A;
    const float* Bp = Bx;
    const float* Sp = Sig;
    if (mode == 1) { Ap = A + (size_t)z*WSZ; Sp = Sig + z*H; Bp = Bx + (size_t)z*H2*H2; }

    int tid = threadIdx.x;
    int tx = tid & 15, ty = tid >> 4;
    int m0 = blockIdx.y << 7, n0 = blockIdx.x << 7;

    unsigned long long acc[8][4];
    #pragma unroll
    for (int i = 0; i < 8; i++)
        #pragma unroll
        for (int j = 0; j < 4; j++) acc[i][j] = 0ull;

    for (int kt = 0; kt < K; kt += 16) {
        #pragma unroll
        for (int i = 0; i < 8; i++) {
            int idx = tid + (i << 8);
            int ak = idx & 15, am = idx >> 4;
            int gm = m0 + am, gk = kt + ak;
            float v = 0.f;
            if (gm < M && gk < K) {
                v = Ap[(size_t)gm*lda + gk];
                if (Sp) v *= Sp[gk];
            }
            As[ak][am] = v;
        }
        #pragma unroll
        for (int i = 0; i < 8; i++) {
            int idx = tid + (i << 8);
            int bk = idx >> 7, bn = idx & 127;
            int gk = kt + bk, gn = n0 + bn;
            Bs[bk][bn] = (gk < K && gn < N) ? Bp[(size_t)gk*ldb + gn] : 0.f;
        }
        __syncthreads();
        #pragma unroll
        for (int kk = 0; kk < 16; kk++) {
            float4 a0 = *(const float4*)&As[kk][ty*8];
            float4 a1 = *(const float4*)&As[kk][ty*8+4];
            ulonglong2 b0 = *(const ulonglong2*)&Bs[kk][tx*8];
            ulonglong2 b1 = *(const ulonglong2*)&Bs[kk][tx*8+4];
            float av[8] = {a0.x,a0.y,a0.z,a0.w,a1.x,a1.y,a1.z,a1.w};
            unsigned long long bv[4] = {b0.x,b0.y,b1.x,b1.y};
            #pragma unroll
            for (int mm = 0; mm < 8; mm++) {
                unsigned long long ap = pack2(av[mm], av[mm]);
                #pragma unroll
                for (int np = 0; np < 4; np++) fma2(acc[mm][np], ap, bv[np]);
            }
        }
        __syncthreads();
    }

    #pragma unroll
    for (int mm = 0; mm < 8; mm++) {
        int gm = m0 + ty*8 + mm;
        if (gm >= M) continue;
        #pragma unroll
        for (int np = 0; np < 4; np++) {
            float2 v = unpack2(acc[mm][np]);
            int gn = n0 + tx*8 + np*2;
            if (gn   < N) store_pre(mode, z, gm, gn,   v.x);
            if (gn+1 < N) store_pre(mode, z, gm, gn+1, v.y);
        }
    }
}

// ---- tf32 XW precompute: g_XW[TT*BB,1700] = X[TT*BB,850] @ g_W0x ----
__global__ void __launch_bounds__(256,2) xw_mma(const float* __restrict__ X)
{
    __shared__ unsigned As[128][17];
    __shared__ unsigned Bs[16][65];

    int tid = threadIdx.x;
    int w = tid >> 5, lane = tid & 31;
    int g = lane >> 2, c = lane & 3;
    int wm = (w & 3) * 32, wn = (w >> 2) * 32;
    int m0 = blockIdx.y << 7, n0 = blockIdx.x << 6;

    float acc[2][4][4];
    #pragma unroll
    for (int i = 0; i < 2; i++)
        #pragma unroll
        for (int j = 0; j < 4; j++)
            #pragma unroll
            for (int r = 0; r < 4; r++) acc[i][j][r] = 0.f;

    for (int kt = 0; kt < H; kt += 16) {
        #pragma unroll
        for (int i = 0; i < 8; i++) {
            int idx = tid + (i << 8);
            int am = idx >> 4, ak = idx & 15;
            int gk = kt + ak;
            As[am][ak] = (gk < H) ? tf32(X[(size_t)(m0+am)*H + gk]) : 0u;
        }
        #pragma unroll
        for (int i = 0; i < 4; i++) {
            int idx = tid + (i << 8);
            int bk = idx >> 6, bn = idx & 63;
            int gk = kt + bk, gn = n0 + bn;
            Bs[bk][bn] = (gk < H && gn < H2) ? tf32(g_W0x[(size_t)gk*H2 + gn]) : 0u;
        }
        __syncthreads();
        #pragma unroll
        for (int k8 = 0; k8 < 16; k8 += 8) {
            unsigned af[2][4], bf[4][2];
            #pragma unroll
            for (int mt = 0; mt < 2; mt++) {
                int R = wm + mt*16;
                af[mt][0] = As[R+g][k8+c];
                af[mt][1] = As[R+g+8][k8+c];
                af[mt][2] = As[R+g][k8+c+4];
                af[mt][3] = As[R+g+8][k8+c+4];
            }
            #pragma unroll
            for (int nt = 0; nt < 4; nt++) {
                int Nb = wn + nt*8;
                bf[nt][0] = Bs[k8+c][Nb+g];
                bf[nt][1] = Bs[k8+c+4][Nb+g];
            }
            #pragma unroll
            for (int mt = 0; mt < 2; mt++)
                #pragma unroll
                for (int nt = 0; nt < 4; nt++)
                    mma8(acc[mt][nt], af[mt], bf[nt]);
        }
        __syncthreads();
    }

    #pragma unroll
    for (int mt = 0; mt < 2; mt++)
        #pragma unroll
        for (int nt = 0; nt < 4; nt++)
            #pragma unroll
            for (int r = 0; r < 4; r++) {
                int row = m0 + wm + mt*16 + g + ((r >> 1) << 3);
                int col = n0 + wn + nt*8 + 2*c + (r & 1);
                if (col < H2) g_XW[(size_t)row*H2 + col] = acc[mt][nt][r];
            }
}

// ---- tf32 recurrent step: out = sp + sigmoid(c)*(act(h) - sp) ----
struct StepD { int a_sel, w, o_sel, act; };
struct LevelArgs { StepD s[3]; const float* hprev; int bias_t; };

__global__ void __launch_bounds__(256,2) step_mma(LevelArgs la)
{
    __shared__ unsigned As[128][17];
    __shared__ unsigned Bs[2][16][33];

    StepD sd = la.s[blockIdx.z];
    const float* A  = (sd.a_sel < 0) ? la.hprev : g_S[sd.a_sel];
    const float* Wc = (sd.w < 0) ? g_W0hc : (g_Wc + (size_t)sd.w*WSZ);
    const float* Wh = (sd.w < 0) ? g_W0hh : (g_Wh + (size_t)sd.w*WSZ);
    float* O = g_S[sd.o_sel];

    int tid = threadIdx.x;
    int w = tid >> 5, lane = tid & 31;
    int g = lane >> 2, c = lane & 3;
    int wm = (w & 3) * 32, wn = (w >> 2) * 16;
    int m0 = blockIdx.y << 7, n0 = blockIdx.x << 5;

    float acc[2][2][2][4];   // [mat][mtile][ntile][reg]
    #pragma unroll
    for (int i = 0; i < 2; i++)
        #pragma unroll
        for (int j = 0; j < 2; j++)
            #pragma unroll
            for (int k = 0; k < 2; k++)
                #pragma unroll
                for (int r = 0; r < 4; r++) acc[i][j][k][r] = 0.f;

    for (int kt = 0; kt < H; kt += 16) {
        #pragma unroll
        for (int i = 0; i < 8; i++) {
            int idx = tid + (i << 8);
            int am = idx >> 4, ak = idx & 15;
            int gk = kt + ak;
            As[am][ak] = (gk < H) ? tf32(A[(m0+am)*H + gk]) : 0u;
        }
        #pragma unroll
        for (int i = 0; i < 4; i++) {
            int idx = tid + (i << 8);
            int mat = idx >> 9, rem = idx & 511;
            int bk = rem >> 5, bn = rem & 31;
            int gk = kt + bk, gn = n0 + bn;
            const float* W = mat ? Wh : Wc;
            Bs[mat][bk][bn] = (gk < H && gn < H) ? tf32(W[(size_t)gk*H + gn]) : 0u;
        }
        __syncthreads();
        #pragma unroll
        for (int k8 = 0; k8 < 16; k8 += 8) {
            unsigned af[2][4], bf[2][2][2];
            #pragma unroll
            for (int mt = 0; mt < 2; mt++) {
                int R = wm + mt*16;
                af[mt][0] = As[R+g][k8+c];
                af[mt][1] = As[R+g+8][k8+c];
                af[mt][2] = As[R+g][k8+c+4];
                af[mt][3] = As[R+g+8][k8+c+4];
            }
            #pragma unroll
            for (int mat = 0; mat < 2; mat++)
                #pragma unroll
                for (int nt = 0; nt < 2; nt++) {
                    int Nb = wn + nt*8;
                    bf[mat][nt][0] = Bs[mat][k8+c][Nb+g];
                    bf[mat][nt][1] = Bs[mat][k8+c+4][Nb+g];
                }
            #pragma unroll
            for (int mat = 0; mat < 2; mat++)
                #pragma unroll
                for (int mt = 0; mt < 2; mt++)
                    #pragma unroll
                    for (int nt = 0; nt < 2; nt++)
                        mma8(acc[mat][mt][nt], af[mt], bf[mat][nt]);
        }
        __syncthreads();
    }

    const float* bias = (la.bias_t >= 0) ? (g_XW + (size_t)la.bias_t*BB*H2) : nullptr;
    #pragma unroll
    for (int mt = 0; mt < 2; mt++)
        #pragma unroll
        for (int nt = 0; nt < 2; nt++)
            #pragma unroll
            for (int r = 0; r < 4; r++) {
                int row = m0 + wm + mt*16 + g + ((r >> 1) << 3);
                int col = n0 + wn + nt*8 + 2*c + (r & 1);
                if (col < H) {
                    float cv = acc[0][mt][nt][r];
                    float hv = acc[1][mt][nt][r];
                    if (bias) {
                        cv += bias[(size_t)row*H2 + col];
                        hv += bias[(size_t)row*H2 + H + col];
                    }
                    float sp   = A[row*H + col];
                    float gate = 1.f / (1.f + expf(-cv));
                    hv = apply_act(hv, sd.act);
                    O[row*H + col] = sp + gate * (hv - sp);
                }
            }
}

__global__ void mean_kernel(float* __restrict__ out, float* __restrict__ out2)
{
    int i = blockIdx.x * 256 + threadIdx.x;
    if (i < BH) {
        float s = g_S[1][i] + g_S[2][i] + g_S[3][i] + g_S[4][i]
                + g_S[5][i] + g_S[6][i] + g_S[7][i] + g_S[8][i];
        s *= 0.125f;
        out[i] = s;
        if (out2) out2[i] = s;
    }
}

extern "C" void kernel_launch(void* const* d_in, const int* in_sizes, int n_in,
                              void* d_out, int out_size) {
    const float* X   = (const float*)d_in[0];
    const float* h0  = (const float*)d_in[1];
    const float* W0U = (const float*)d_in[2];
    const float* W0s = (const float*)d_in[3];
    const float* W0V = (const float*)d_in[4];
    const float* WsU = (const float*)d_in[5];
    const float* Wss = (const float*)d_in[6];
    const float* WsV = (const float*)d_in[7];
    float* out = (float*)d_out;

    dim3 thr(256);
    gemm_pre<<<dim3(14,14,1), thr>>>(0, W0U, W0s, W0V, H2, H2, H2, H2, H2);
    gemm_pre<<<dim3(14,7,8),  thr>>>(1, WsU, Wss, WsV, H,  H2, H,  H,  H2);
    xw_mma<<<dim3(27,256,1), thr>>>(X);

    for (int t = 0; t < TT; t++) {
        LevelArgs L;
        L.hprev = (t == 0) ? h0 : out + (size_t)(t-1)*BH;
        L.bias_t = t;
        L.s[0] = {-1,-1,0,ACT_TANH};
        step_mma<<<dim3(27,2,1), thr>>>(L);
        L.bias_t = -1;
        L.s[0] = {0,0,1,ACT_SIG};
        step_mma<<<dim3(27,2,1), thr>>>(L);
        L.s[0] = {1,1,2,ACT_RELU}; L.s[1] = {1,2,3,ACT_RELU}; L.s[2] = {1,3,4,ACT_ID};
        step_mma<<<dim3(27,2,3), thr>>>(L);
        L.s[0] = {2,4,5,ACT_TANH}; L.s[1] = {3,6,7,ACT_TANH};
        step_mma<<<dim3(27,2,2), thr>>>(L);
        L.s[0] = {5,5,6,ACT_SIG};  L.s[1] = {5,7,8,ACT_RELU};
        step_mma<<<dim3(27,2,2), thr>>>(L);
        float* o2 = (t == TT-1) ? (out + (size_t)TT*BH) : nullptr;
        mean_kernel<<<dim3((BH+255)/256), thr>>>(out + (size_t)t*BH, o2);
    }
}

// round 4
// speedup vs baseline: 2.5317x; 1.6916x over previous
#include <cuda_runtime.h>
#include <math.h>

#define H    850
#define H2   1700
#define BB   256
#define TT   128
#define BH   (BB*H)
#define SP   864          // padded K/N stride (54*16)

__device__ float g_W0x[H*H2];
__device__ float g_W0hc[SP*SP];
__device__ float g_W0hh[SP*SP];
__device__ float g_Wc[8][SP*SP];
__device__ float g_Wh[8][SP*SP];
__device__ float g_XW[(size_t)TT*BB*H2];
__device__ float g_S[9][BB*SP];
__device__ float g_Hprev[BB*SP];

__device__ volatile unsigned g_gen;
__device__ unsigned g_cnt;

__device__ __forceinline__ unsigned long long pack2(float x, float y) {
    unsigned long long r;
    asm("mov.b64 %0, {%1, %2};" : "=l"(r) : "f"(x), "f"(y));
    return r;
}
__device__ __forceinline__ void fma2(unsigned long long& d,
                                     unsigned long long a, unsigned long long b) {
    asm("fma.rn.f32x2 %0, %1, %2, %0;" : "+l"(d) : "l"(a), "l"(b));
}
__device__ __forceinline__ float2 unpack2(unsigned long long v) {
    float2 f;
    asm("mov.b64 {%0, %1}, %2;" : "=f"(f.x), "=f"(f.y) : "l"(v));
    return f;
}
__device__ __forceinline__ unsigned tf32(float x) {
    unsigned r;
    asm("cvt.rna.tf32.f32 %0, %1;" : "=r"(r) : "f"(x));
    return r;
}
__device__ __forceinline__ void mma8(float* d, const unsigned* a, const unsigned* b) {
    asm("mma.sync.aligned.m16n8k8.row.col.f32.tf32.tf32.f32 "
        "{%0,%1,%2,%3}, {%4,%5,%6,%7}, {%8,%9}, {%0,%1,%2,%3};"
        : "+f"(d[0]), "+f"(d[1]), "+f"(d[2]), "+f"(d[3])
        : "r"(a[0]), "r"(a[1]), "r"(a[2]), "r"(a[3]), "r"(b[0]), "r"(b[1]));
}
__device__ __forceinline__ void cp16(void* dst, const void* src) {
    unsigned u = (unsigned)__cvta_generic_to_shared(dst);
    asm volatile("cp.async.cg.shared.global [%0], [%1], 16;" :: "r"(u), "l"(src));
}

#define ACT_TANH 0
#define ACT_RELU 1
#define ACT_SIG  2
#define ACT_ID   3

__device__ __forceinline__ float apply_act(float x, int a) {
    switch (a) {
        case ACT_TANH: return tanhf(x);
        case ACT_RELU: return fmaxf(x, 0.f);
        case ACT_SIG:  return 1.f / (1.f + expf(-x));
        default:       return x;
    }
}

// ---- fp32 weight-fusion GEMM ----
__device__ __forceinline__ float rnd32(float v) { return __uint_as_float(tf32(v)); }

__device__ __forceinline__ void store_pre(int mode, int z, int m, int n, float v) {
    if (mode == 0) {
        if (m < H)      g_W0x[m*H2 + n] = v;
        else if (n < H) g_W0hc[(m-H)*SP + n] = rnd32(v);
        else            g_W0hh[(m-H)*SP + (n-H)] = rnd32(v);
    } else {
        if (n < H) g_Wc[z][m*SP + n] = rnd32(v);
        else       g_Wh[z][m*SP + (n-H)] = rnd32(v);
    }
}

__global__ void __launch_bounds__(256,2) gemm_pre(
    int mode, const float* __restrict__ A, const float* __restrict__ Sig,
    const float* __restrict__ Bx, int M, int N, int K, int lda, int ldb)
{
    __shared__ __align__(16) float As[16][136];
    __shared__ __align__(16) float Bs[16][128];

    int z = blockIdx.z;
    const float* Ap = A;
    const float* Bp = Bx;
    const float* Sp = Sig;
    if (mode == 1) { Ap = A + (size_t)z*H*H; Sp = Sig + z*H; Bp = Bx + (size_t)z*H2*H2; }

    int tid = threadIdx.x;
    int tx = tid & 15, ty = tid >> 4;
    int m0 = blockIdx.y << 7, n0 = blockIdx.x << 7;

    unsigned long long acc[8][4];
    #pragma unroll
    for (int i = 0; i < 8; i++)
        #pragma unroll
        for (int j = 0; j < 4; j++) acc[i][j] = 0ull;

    for (int kt = 0; kt < K; kt += 16) {
        #pragma unroll
        for (int i = 0; i < 8; i++) {
            int idx = tid + (i << 8);
            int ak = idx & 15, am = idx >> 4;
            int gm = m0 + am, gk = kt + ak;
            float v = 0.f;
            if (gm < M && gk < K) {
                v = Ap[(size_t)gm*lda + gk];
                if (Sp) v *= Sp[gk];
            }
            As[ak][am] = v;
        }
        #pragma unroll
        for (int i = 0; i < 8; i++) {
            int idx = tid + (i << 8);
            int bk = idx >> 7, bn = idx & 127;
            int gk = kt + bk, gn = n0 + bn;
            Bs[bk][bn] = (gk < K && gn < N) ? Bp[(size_t)gk*ldb + gn] : 0.f;
        }
        __syncthreads();
        #pragma unroll
        for (int kk = 0; kk < 16; kk++) {
            float4 a0 = *(const float4*)&As[kk][ty*8];
            float4 a1 = *(const float4*)&As[kk][ty*8+4];
            ulonglong2 b0 = *(const ulonglong2*)&Bs[kk][tx*8];
            ulonglong2 b1 = *(const ulonglong2*)&Bs[kk][tx*8+4];
            float av[8] = {a0.x,a0.y,a0.z,a0.w,a1.x,a1.y,a1.z,a1.w};
            unsigned long long bv[4] = {b0.x,b0.y,b1.x,b1.y};
            #pragma unroll
            for (int mm = 0; mm < 8; mm++) {
                unsigned long long ap = pack2(av[mm], av[mm]);
                #pragma unroll
                for (int np = 0; np < 4; np++) fma2(acc[mm][np], ap, bv[np]);
            }
        }
        __syncthreads();
    }

    #pragma unroll
    for (int mm = 0; mm < 8; mm++) {
        int gm = m0 + ty*8 + mm;
        if (gm >= M) continue;
        #pragma unroll
        for (int np = 0; np < 4; np++) {
            float2 v = unpack2(acc[mm][np]);
            int gn = n0 + tx*8 + np*2;
            if (gn   < N) store_pre(mode, z, gm, gn,   v.x);
            if (gn+1 < N) store_pre(mode, z, gm, gn+1, v.y);
        }
    }
}

// ---- tf32 XW precompute ----
__global__ void __launch_bounds__(256,2) xw_mma(const float* __restrict__ X)
{
    __shared__ unsigned As[128][17];
    __shared__ unsigned Bs[16][65];

    int tid = threadIdx.x;
    int w = tid >> 5, lane = tid & 31;
    int g = lane >> 2, c = lane & 3;
    int wm = (w & 3) * 32, wn = (w >> 2) * 32;
    int m0 = blockIdx.y << 7, n0 = blockIdx.x << 6;

    float acc[2][4][4];
    #pragma unroll
    for (int i = 0; i < 2; i++)
        #pragma unroll
        for (int j = 0; j < 4; j++)
            #pragma unroll
            for (int r = 0; r < 4; r++) acc[i][j][r] = 0.f;

    for (int kt = 0; kt < H; kt += 16) {
        #pragma unroll
        for (int i = 0; i < 8; i++) {
            int idx = tid + (i << 8);
            int am = idx >> 4, ak = idx & 15;
            int gk = kt + ak;
            As[am][ak] = (gk < H) ? tf32(X[(size_t)(m0+am)*H + gk]) : 0u;
        }
        #pragma unroll
        for (int i = 0; i < 4; i++) {
            int idx = tid + (i << 8);
            int bk = idx >> 6, bn = idx & 63;
            int gk = kt + bk, gn = n0 + bn;
            Bs[bk][bn] = (gk < H && gn < H2) ? tf32(g_W0x[(size_t)gk*H2 + gn]) : 0u;
        }
        __syncthreads();
        #pragma unroll
        for (int k8 = 0; k8 < 16; k8 += 8) {
            unsigned af[2][4], bf[4][2];
            #pragma unroll
            for (int mt = 0; mt < 2; mt++) {
                int R = wm + mt*16;
                af[mt][0] = As[R+g][k8+c];
                af[mt][1] = As[R+g+8][k8+c];
                af[mt][2] = As[R+g][k8+c+4];
                af[mt][3] = As[R+g+8][k8+c+4];
            }
            #pragma unroll
            for (int nt = 0; nt < 4; nt++) {
                int Nb = wn + nt*8;
                bf[nt][0] = Bs[k8+c][Nb+g];
                bf[nt][1] = Bs[k8+c+4][Nb+g];
            }
            #pragma unroll
            for (int mt = 0; mt < 2; mt++)
                #pragma unroll
                for (int nt = 0; nt < 4; nt++)
                    mma8(acc[mt][nt], af[mt], bf[nt]);
        }
        __syncthreads();
    }

    #pragma unroll
    for (int mt = 0; mt < 2; mt++)
        #pragma unroll
        for (int nt = 0; nt < 4; nt++)
            #pragma unroll
            for (int r = 0; r < 4; r++) {
                int row = m0 + wm + mt*16 + g + ((r >> 1) << 3);
                int col = n0 + wn + nt*8 + 2*c + (r & 1);
                if (col < H2) g_XW[(size_t)row*H2 + col] = acc[mt][nt][r];
            }
}

// ---- device-wide barrier (all blocks co-resident) ----
__device__ __forceinline__ void gsync(unsigned nb) {
    __syncthreads();
    if (threadIdx.x == 0) {
        __threadfence();
        unsigned my = g_gen;
        if (atomicAdd(&g_cnt, 1u) == nb - 1) {
            g_cnt = 0;
            __threadfence();
            g_gen = my + 1;
        } else {
            while (g_gen == my) __nanosleep(64);
            __threadfence();
        }
    }
    __syncthreads();
}

// ---- one 128x32 tile of a fused step GEMM (c & h), double-buffered ----
__device__ __forceinline__ void do_tile(
    const float* __restrict__ Aact, const float* __restrict__ Wc,
    const float* __restrict__ Wh, float* __restrict__ Obuf,
    const float* __restrict__ bias, int act, int m0, int n0,
    unsigned (&As)[2][128][20], unsigned (&Bs)[2][2][16][36])
{
    int tid = threadIdx.x;
    int w = tid >> 5, lane = tid & 31;
    int g = lane >> 2, c = lane & 3;
    int wm = (w & 3) * 32, wn = (w >> 2) * 16;

    float acc[2][2][2][4];
    #pragma unroll
    for (int i = 0; i < 2; i++)
        #pragma unroll
        for (int j = 0; j < 2; j++)
            #pragma unroll
            for (int k = 0; k < 2; k++)
                #pragma unroll
                for (int r = 0; r < 4; r++) acc[i][j][k][r] = 0.f;

    // prologue: issue iter 0
    {
        int kt = 0;
        #pragma unroll
        for (int i = 0; i < 2; i++) {
            int idx = tid + (i << 8);
            int am = idx >> 2, q = idx & 3;
            cp16(&As[0][am][q*4], Aact + (size_t)(m0+am)*SP + kt + q*4);
        }
        {
            int mat = tid >> 7, rem = tid & 127;
            int k = rem >> 3, q = rem & 7;
            const float* W = mat ? Wh : Wc;
            cp16(&Bs[0][mat][k][q*4], W + (size_t)(kt+k)*SP + n0 + q*4);
        }
        asm volatile("cp.async.commit_group;");
    }

    for (int it = 0; it < 54; it++) {
        int buf = it & 1;
        if (it + 1 < 54) {
            int kt = (it+1) * 16;
            int nb = buf ^ 1;
            #pragma unroll
            for (int i = 0; i < 2; i++) {
                int idx = tid + (i << 8);
                int am = idx >> 2, q = idx & 3;
                cp16(&As[nb][am][q*4], Aact + (size_t)(m0+am)*SP + kt + q*4);
            }
            {
                int mat = tid >> 7, rem = tid & 127;
                int k = rem >> 3, q = rem & 7;
                const float* W = mat ? Wh : Wc;
                cp16(&Bs[nb][mat][k][q*4], W + (size_t)(kt+k)*SP + n0 + q*4);
            }
            asm volatile("cp.async.commit_group;");
            asm volatile("cp.async.wait_group 1;");
        } else {
            asm volatile("cp.async.wait_group 0;");
        }
        __syncthreads();
        #pragma unroll
        for (int k8 = 0; k8 < 16; k8 += 8) {
            unsigned af[2][4], bf[2][2][2];
            #pragma unroll
            for (int mt = 0; mt < 2; mt++) {
                int R = wm + mt*16;
                af[mt][0] = As[buf][R+g][k8+c];
                af[mt][1] = As[buf][R+g+8][k8+c];
                af[mt][2] = As[buf][R+g][k8+c+4];
                af[mt][3] = As[buf][R+g+8][k8+c+4];
            }
            #pragma unroll
            for (int mat = 0; mat < 2; mat++)
                #pragma unroll
                for (int nt = 0; nt < 2; nt++) {
                    int Nb = wn + nt*8;
                    bf[mat][nt][0] = Bs[buf][mat][k8+c][Nb+g];
                    bf[mat][nt][1] = Bs[buf][mat][k8+c+4][Nb+g];
                }
            #pragma unroll
            for (int mat = 0; mat < 2; mat++)
                #pragma unroll
                for (int mt = 0; mt < 2; mt++)
                    #pragma unroll
                    for (int nt = 0; nt < 2; nt++)
                        mma8(acc[mat][mt][nt], af[mt], bf[mat][nt]);
        }
        __syncthreads();
    }

    #pragma unroll
    for (int mt = 0; mt < 2; mt++)
        #pragma unroll
        for (int nt = 0; nt < 2; nt++)
            #pragma unroll
            for (int r = 0; r < 4; r++) {
                int row = m0 + wm + mt*16 + g + ((r >> 1) << 3);
                int col = n0 + wn + nt*8 + 2*c + (r & 1);
                if (col < H) {
                    float cv = acc[0][mt][nt][r];
                    float hv = acc[1][mt][nt][r];
                    if (bias) {
                        cv += bias[(size_t)row*H2 + col];
                        hv += bias[(size_t)row*H2 + H + col];
                    }
                    float sp   = Aact[(size_t)row*SP + col];
                    float gate = 1.f / (1.f + expf(-cv));
                    hv = apply_act(hv, act);
                    Obuf[(size_t)row*SP + col] = sp + gate * (hv - sp);
                }
            }
}

// ---- persistent whole-recurrence kernel ----
__global__ void __launch_bounds__(256) rnn_persist(
    const float* __restrict__ h0, float* __restrict__ out)
{
    __shared__ __align__(16) unsigned As[2][128][20];
    __shared__ __align__(16) unsigned Bs[2][2][16][36];

    const unsigned NB = gridDim.x;
    const int tid = threadIdx.x;

    const int l_start[5] = {0,1,2,5,7};
    const int l_cnt[5]   = {1,1,3,2,2};
    const int st_a[9]   = {-1,0,1,1,1,2,3,5,5};
    const int st_w[9]   = {-1,0,1,2,3,4,6,5,7};
    const int st_o[9]   = {0,1,2,3,4,5,7,6,8};
    const int st_act[9] = {ACT_TANH,ACT_SIG,ACT_RELU,ACT_RELU,ACT_ID,
                           ACT_TANH,ACT_TANH,ACT_SIG,ACT_RELU};

    for (int i = blockIdx.x*256 + tid; i < BH; i += NB*256)
        g_Hprev[(i/H)*SP + (i%H)] = h0[i];
    gsync(NB);

    for (int t = 0; t < TT; t++) {
        for (int lvl = 0; lvl < 5; lvl++) {
            int base = l_start[lvl];
            int njobs = l_cnt[lvl] * 54;
            for (int job = blockIdx.x; job < njobs; job += NB) {
                int si = base + job / 54;
                int r  = job % 54;
                int m0 = (r / 27) * 128;
                int n0 = (r % 27) * 32;
                const float* Aact = (st_a[si] < 0) ? g_Hprev : g_S[st_a[si]];
                const float* Wc   = (st_w[si] < 0) ? g_W0hc : g_Wc[st_w[si]];
                const float* Wh   = (st_w[si] < 0) ? g_W0hh : g_Wh[st_w[si]];
                const float* bias = (st_a[si] < 0) ? (g_XW + (size_t)t*BB*H2) : nullptr;
                do_tile(Aact, Wc, Wh, g_S[st_o[si]], bias, st_act[si], m0, n0, As, Bs);
            }
            gsync(NB);
        }
        float* od = out + (size_t)t*BH;
        for (int i = blockIdx.x*256 + tid; i < BH; i += NB*256) {
            int pi = (i/H)*SP + (i%H);
            float s = g_S[1][pi] + g_S[2][pi] + g_S[3][pi] + g_S[4][pi]
                    + g_S[5][pi] + g_S[6][pi] + g_S[7][pi] + g_S[8][pi];
            s *= 0.125f;
            od[i] = s;
            g_Hprev[pi] = s;
            if (t == TT-1) out[(size_t)TT*BH + i] = s;
        }
        gsync(NB);
    }
}

extern "C" void kernel_launch(void* const* d_in, const int* in_sizes, int n_in,
                              void* d_out, int out_size) {
    const float* X   = (const float*)d_in[0];
    const float* h0  = (const float*)d_in[1];
    const float* W0U = (const float*)d_in[2];
    const float* W0s = (const float*)d_in[3];
    const float* W0V = (const float*)d_in[4];
    const float* WsU = (const float*)d_in[5];
    const float* Wss = (const float*)d_in[6];
    const float* WsV = (const float*)d_in[7];
    float* out = (float*)d_out;

    dim3 thr(256);
    gemm_pre<<<dim3(14,14,1), thr>>>(0, W0U, W0s, W0V, H2, H2, H2, H2, H2);
    gemm_pre<<<dim3(14,7,8),  thr>>>(1, WsU, Wss, WsV, H,  H2, H,  H,  H2);
    xw_mma<<<dim3(27,256,1), thr>>>(X);
    rnn_persist<<<148, thr>>>(h0, out);
}

// round 5
// speedup vs baseline: 2.7400x; 1.0823x over previous
#include <cuda_runtime.h>
#include <math.h>

#define H    850
#define H2   1700
#define BB   256
#define TT   128
#define BH   (BB*H)
#define SP   896          // padded K/N stride (28*32)
#define NIT  28           // K iterations at BK=32

__device__ float g_W0x[H*H2];
__device__ float g_W0hc[SP*SP];
__device__ float g_W0hh[SP*SP];
__device__ float g_Wc[8][SP*SP];
__device__ float g_Wh[8][SP*SP];
__device__ float g_XW[(size_t)TT*BB*H2];
__device__ float g_S[9][BB*SP];
__device__ float g_Hprev[BB*SP];

__device__ volatile unsigned g_gen;
__device__ unsigned g_cnt;

__device__ __forceinline__ unsigned tf32(float x) {
    unsigned r;
    asm("cvt.rna.tf32.f32 %0, %1;" : "=r"(r) : "f"(x));
    return r;
}
__device__ __forceinline__ float rnd32(float v) { return __uint_as_float(tf32(v)); }

__device__ __forceinline__ void mma8(float* d, const unsigned* a, const unsigned* b) {
    asm("mma.sync.aligned.m16n8k8.row.col.f32.tf32.tf32.f32 "
        "{%0,%1,%2,%3}, {%4,%5,%6,%7}, {%8,%9}, {%0,%1,%2,%3};"
        : "+f"(d[0]), "+f"(d[1]), "+f"(d[2]), "+f"(d[3])
        : "r"(a[0]), "r"(a[1]), "r"(a[2]), "r"(a[3]), "r"(b[0]), "r"(b[1]));
}
__device__ __forceinline__ void cp16(void* dst, const void* src) {
    unsigned u = (unsigned)__cvta_generic_to_shared(dst);
    asm volatile("cp.async.cg.shared.global [%0], [%1], 16;" :: "r"(u), "l"(src));
}

#define ACT_TANH 0
#define ACT_RELU 1
#define ACT_SIG  2
#define ACT_ID   3

__device__ __forceinline__ float apply_act(float x, int a) {
    switch (a) {
        case ACT_TANH: return tanhf(x);
        case ACT_RELU: return fmaxf(x, 0.f);
        case ACT_SIG:  return 1.f / (1.f + expf(-x));
        default:       return x;
    }
}

// ---- tf32 weight fusion: C[m,n] = (A[m,:].*sig) @ B ----
// mode 0: W0 (M=K=1700) -> g_W0x / g_W0hc / g_W0hh
// mode 1: Ws[z] (M=K=850) -> g_Wc[z] / g_Wh[z]
__global__ void __launch_bounds__(256) fuse_mma(
    int mode, const float* __restrict__ A, const float* __restrict__ Sig,
    const float* __restrict__ Bx)
{
    __shared__ unsigned As[128][17];
    __shared__ unsigned Bs[16][65];

    int z = blockIdx.z;
    int M = mode ? H : H2;
    int K = M;
    int lda = M;
    const float* Ap = A;
    const float* Sp = Sig;
    const float* Bp = Bx;
    if (mode == 1) { Ap = A + (size_t)z*H*H; Sp = Sig + z*H; Bp = Bx + (size_t)z*H2*H2; }

    int tid = threadIdx.x;
    int w = tid >> 5, lane = tid & 31;
    int g = lane >> 2, c = lane & 3;
    int wm = (w & 3) * 32, wn = (w >> 2) * 32;
    int m0 = blockIdx.y << 7, n0 = blockIdx.x << 6;

    float acc[2][4][4];
    #pragma unroll
    for (int i = 0; i < 2; i++)
        #pragma unroll
        for (int j = 0; j < 4; j++)
            #pragma unroll
            for (int r = 0; r < 4; r++) acc[i][j][r] = 0.f;

    for (int kt = 0; kt < K; kt += 16) {
        #pragma unroll
        for (int i = 0; i < 8; i++) {
            int idx = tid + (i << 8);
            int am = idx >> 4, ak = idx & 15;
            int gm = m0 + am, gk = kt + ak;
            As[am][ak] = (gm < M && gk < K) ? tf32(Ap[(size_t)gm*lda + gk] * Sp[gk]) : 0u;
        }
        #pragma unroll
        for (int i = 0; i < 4; i++) {
            int idx = tid + (i << 8);
            int bk = idx >> 6, bn = idx & 63;
            int gk = kt + bk, gn = n0 + bn;
            Bs[bk][bn] = (gk < K && gn < H2) ? tf32(Bp[(size_t)gk*H2 + gn]) : 0u;
        }
        __syncthreads();
        #pragma unroll
        for (int k8 = 0; k8 < 16; k8 += 8) {
            unsigned af[2][4], bf[4][2];
            #pragma unroll
            for (int mt = 0; mt < 2; mt++) {
                int R = wm + mt*16;
                af[mt][0] = As[R+g][k8+c];
                af[mt][1] = As[R+g+8][k8+c];
                af[mt][2] = As[R+g][k8+c+4];
                af[mt][3] = As[R+g+8][k8+c+4];
            }
            #pragma unroll
            for (int nt = 0; nt < 4; nt++) {
                int Nb = wn + nt*8;
                bf[nt][0] = Bs[k8+c][Nb+g];
                bf[nt][1] = Bs[k8+c+4][Nb+g];
            }
            #pragma unroll
            for (int mt = 0; mt < 2; mt++)
                #pragma unroll
                for (int nt = 0; nt < 4; nt++)
                    mma8(acc[mt][nt], af[mt], bf[nt]);
        }
        __syncthreads();
    }

    #pragma unroll
    for (int mt = 0; mt < 2; mt++)
        #pragma unroll
        for (int nt = 0; nt < 4; nt++)
            #pragma unroll
            for (int r = 0; r < 4; r++) {
                int row = m0 + wm + mt*16 + g + ((r >> 1) << 3);
                int col = n0 + wn + nt*8 + 2*c + (r & 1);
                if (col >= H2 || row >= M) continue;
                float v = acc[mt][nt][r];
                if (mode == 0) {
                    if (row < H)      g_W0x[row*H2 + col] = v;
                    else if (col < H) g_W0hc[(row-H)*SP + col] = rnd32(v);
                    else              g_W0hh[(row-H)*SP + (col-H)] = rnd32(v);
                } else {
                    if (col < H) g_Wc[z][row*SP + col] = rnd32(v);
                    else         g_Wh[z][row*SP + (col-H)] = rnd32(v);
                }
            }
}

// ---- tf32 XW precompute: g_XW = X[32768,850] @ g_W0x[850,1700] ----
__global__ void __launch_bounds__(256) xw_mma(const float* __restrict__ X)
{
    __shared__ unsigned As[128][17];
    __shared__ unsigned Bs[16][65];

    int tid = threadIdx.x;
    int w = tid >> 5, lane = tid & 31;
    int g = lane >> 2, c = lane & 3;
    int wm = (w & 3) * 32, wn = (w >> 2) * 32;
    int m0 = blockIdx.y << 7, n0 = blockIdx.x << 6;

    float acc[2][4][4];
    #pragma unroll
    for (int i = 0; i < 2; i++)
        #pragma unroll
        for (int j = 0; j < 4; j++)
            #pragma unroll
            for (int r = 0; r < 4; r++) acc[i][j][r] = 0.f;

    for (int kt = 0; kt < H; kt += 16) {
        #pragma unroll
        for (int i = 0; i < 8; i++) {
            int idx = tid + (i << 8);
            int am = idx >> 4, ak = idx & 15;
            int gk = kt + ak;
            As[am][ak] = (gk < H) ? tf32(X[(size_t)(m0+am)*H + gk]) : 0u;
        }
        #pragma unroll
        for (int i = 0; i < 4; i++) {
            int idx = tid + (i << 8);
            int bk = idx >> 6, bn = idx & 63;
            int gk = kt + bk, gn = n0 + bn;
            Bs[bk][bn] = (gk < H && gn < H2) ? tf32(g_W0x[(size_t)gk*H2 + gn]) : 0u;
        }
        __syncthreads();
        #pragma unroll
        for (int k8 = 0; k8 < 16; k8 += 8) {
            unsigned af[2][4], bf[4][2];
            #pragma unroll
            for (int mt = 0; mt < 2; mt++) {
                int R = wm + mt*16;
                af[mt][0] = As[R+g][k8+c];
                af[mt][1] = As[R+g+8][k8+c];
                af[mt][2] = As[R+g][k8+c+4];
                af[mt][3] = As[R+g+8][k8+c+4];
            }
            #pragma unroll
            for (int nt = 0; nt < 4; nt++) {
                int Nb = wn + nt*8;
                bf[nt][0] = Bs[k8+c][Nb+g];
                bf[nt][1] = Bs[k8+c+4][Nb+g];
            }
            #pragma unroll
            for (int mt = 0; mt < 2; mt++)
                #pragma unroll
                for (int nt = 0; nt < 4; nt++)
                    mma8(acc[mt][nt], af[mt], bf[nt]);
        }
        __syncthreads();
    }

    #pragma unroll
    for (int mt = 0; mt < 2; mt++)
        #pragma unroll
        for (int nt = 0; nt < 4; nt++)
            #pragma unroll
            for (int r = 0; r < 4; r++) {
                int row = m0 + wm + mt*16 + g + ((r >> 1) << 3);
                int col = n0 + wn + nt*8 + 2*c + (r & 1);
                if (col < H2) g_XW[(size_t)row*H2 + col] = acc[mt][nt][r];
            }
}

// ---- device-wide barrier ----
__device__ __forceinline__ void gsync(unsigned nb) {
    __syncthreads();
    if (threadIdx.x == 0) {
        __threadfence();
        unsigned my = g_gen;
        if (atomicAdd(&g_cnt, 1u) == nb - 1) {
            g_cnt = 0;
            __threadfence();
            g_gen = my + 1;
        } else {
            while (g_gen == my) __nanosleep(64);
            __threadfence();
        }
    }
    __syncthreads();
}

// ---- one 64x64 tile of a fused step GEMM (c & h) ----
// As: [2][64][36], Bs: [2][2][32][68] in dynamic smem
__device__ __forceinline__ void tile_loads(
    unsigned (*As)[64][36], unsigned (*Bs)[2][32][68],
    const float* Aact, const float* Wc, const float* Wh,
    int b, int m0, int n0, int kt, int tid)
{
    #pragma unroll
    for (int i = 0; i < 2; i++) {
        int idx = tid + (i << 8);
        int am = idx >> 3, q = idx & 7;
        cp16(&As[b][am][q*4], Aact + (size_t)(m0+am)*SP + kt + q*4);
    }
    #pragma unroll
    for (int i = 0; i < 4; i++) {
        int idx = tid + (i << 8);
        int mat = idx >> 9, rem = idx & 511;
        int k = rem >> 4, q = rem & 15;
        const float* W = mat ? Wh : Wc;
        cp16(&Bs[b][mat][k][q*4], W + (size_t)(kt+k)*SP + n0 + q*4);
    }
    asm volatile("cp.async.commit_group;");
}

__device__ __forceinline__ void frag_loads(
    unsigned (*As)[64][36], unsigned (*Bs)[2][32][68],
    unsigned (&af)[2][4], unsigned (&bf)[2][2][2],
    int buf, int k8, int wm, int wn, int g, int c)
{
    #pragma unroll
    for (int mt = 0; mt < 2; mt++) {
        int R = wm + mt*16;
        af[mt][0] = As[buf][R+g][k8+c];
        af[mt][1] = As[buf][R+g+8][k8+c];
        af[mt][2] = As[buf][R+g][k8+c+4];
        af[mt][3] = As[buf][R+g+8][k8+c+4];
    }
    #pragma unroll
    for (int mat = 0; mat < 2; mat++)
        #pragma unroll
        for (int nt = 0; nt < 2; nt++) {
            int Nb = wn + nt*8;
            bf[mat][nt][0] = Bs[buf][mat][k8+c][Nb+g];
            bf[mat][nt][1] = Bs[buf][mat][k8+c+4][Nb+g];
        }
}

__device__ __forceinline__ void do_tile(
    unsigned (*As)[64][36], unsigned (*Bs)[2][32][68],
    const float* __restrict__ Aact, const float* __restrict__ Wc,
    const float* __restrict__ Wh, float* __restrict__ Obuf,
    const float* __restrict__ bias, int act, int m0, int n0)
{
    int tid = threadIdx.x;
    int w = tid >> 5, lane = tid & 31;
    int g = lane >> 2, c = lane & 3;
    int wm = (w & 1) * 32, wn = (w >> 1) * 16;

    float acc[2][2][2][4];
    #pragma unroll
    for (int i = 0; i < 2; i++)
        #pragma unroll
        for (int j = 0; j < 2; j++)
            #pragma unroll
            for (int k = 0; k < 2; k++)
                #pragma unroll
                for (int r = 0; r < 4; r++) acc[i][j][k][r] = 0.f;

    tile_loads(As, Bs, Aact, Wc, Wh, 0, m0, n0, 0, tid);

    for (int it = 0; it < NIT; it++) {
        int buf = it & 1;
        asm volatile("cp.async.wait_group 0;");
        __syncthreads();
        if (it + 1 < NIT)
            tile_loads(As, Bs, Aact, Wc, Wh, buf ^ 1, m0, n0, (it+1)*32, tid);

        unsigned af[2][2][4], bf[2][2][2][2];
        frag_loads(As, Bs, af[0], bf[0], buf, 0, wm, wn, g, c);
        #pragma unroll
        for (int k8i = 0; k8i < 4; k8i++) {
            int cur = k8i & 1;
            if (k8i < 3)
                frag_loads(As, Bs, af[cur^1], bf[cur^1], buf, (k8i+1)*8, wm, wn, g, c);
            #pragma unroll
            for (int mat = 0; mat < 2; mat++)
                #pragma unroll
                for (int mt = 0; mt < 2; mt++)
                    #pragma unroll
                    for (int nt = 0; nt < 2; nt++)
                        mma8(acc[mat][mt][nt], af[cur][mt], bf[cur][mat][nt]);
        }
    }

    #pragma unroll
    for (int mt = 0; mt < 2; mt++)
        #pragma unroll
        for (int nt = 0; nt < 2; nt++)
            #pragma unroll
            for (int r = 0; r < 4; r++) {
                int row = m0 + wm + mt*16 + g + ((r >> 1) << 3);
                int col = n0 + wn + nt*8 + 2*c + (r & 1);
                if (col < H) {
                    float cv = acc[0][mt][nt][r];
                    float hv = acc[1][mt][nt][r];
                    if (bias) {
                        cv += bias[(size_t)row*H2 + col];
                        hv += bias[(size_t)row*H2 + H + col];
                    }
                    float sp   = Aact[(size_t)row*SP + col];
                    float gate = 1.f / (1.f + expf(-cv));
                    hv = apply_act(hv, act);
                    Obuf[(size_t)row*SP + col] = sp + gate * (hv - sp);
                }
            }
}

// ---- persistent whole-recurrence kernel ----
__global__ void __launch_bounds__(256) rnn_persist(
    const float* __restrict__ h0, float* __restrict__ out)
{
    extern __shared__ unsigned dsm[];
    unsigned (*As)[64][36]    = (unsigned(*)[64][36])dsm;
    unsigned (*Bs)[2][32][68] = (unsigned(*)[2][32][68])(dsm + 2*64*36);

    const unsigned NB = gridDim.x;
    const int tid = threadIdx.x;

    const int l_start[5] = {0,1,2,5,7};
    const int l_cnt[5]   = {1,1,3,2,2};
    const int st_a[9]   = {-1,0,1,1,1,2,3,5,5};
    const int st_w[9]   = {-1,0,1,2,3,4,6,5,7};
    const int st_o[9]   = {0,1,2,3,4,5,7,6,8};
    const int st_act[9] = {ACT_TANH,ACT_SIG,ACT_RELU,ACT_RELU,ACT_ID,
                           ACT_TANH,ACT_TANH,ACT_SIG,ACT_RELU};

    for (int i = blockIdx.x*256 + tid; i < BH; i += NB*256)
        g_Hprev[(i/H)*SP + (i%H)] = h0[i];
    gsync(NB);

    for (int t = 0; t < TT; t++) {
        for (int lvl = 0; lvl < 5; lvl++) {
            int base = l_start[lvl];
            int njobs = l_cnt[lvl] * 56;
            for (int job = blockIdx.x; job < njobs; job += NB) {
                int si = base + job / 56;
                int r  = job % 56;
                int m0 = (r / 14) * 64;
                int n0 = (r % 14) * 64;
                const float* Aact = (st_a[si] < 0) ? g_Hprev : g_S[st_a[si]];
                const float* Wc   = (st_w[si] < 0) ? g_W0hc : g_Wc[st_w[si]];
                const float* Wh   = (st_w[si] < 0) ? g_W0hh : g_Wh[st_w[si]];
                const float* bias = (st_a[si] < 0) ? (g_XW + (size_t)t*BB*H2) : nullptr;
                do_tile(As, Bs, Aact, Wc, Wh, g_S[st_o[si]], bias, st_act[si], m0, n0);
            }
            gsync(NB);
        }
        float* od = out + (size_t)t*BH;
        for (int i = blockIdx.x*256 + tid; i < BH; i += NB*256) {
            int pi = (i/H)*SP + (i%H);
            float s = g_S[1][pi] + g_S[2][pi] + g_S[3][pi] + g_S[4][pi]
                    + g_S[5][pi] + g_S[6][pi] + g_S[7][pi] + g_S[8][pi];
            s *= 0.125f;
            od[i] = s;
            g_Hprev[pi] = s;
            if (t == TT-1) out[(size_t)TT*BH + i] = s;
        }
        gsync(NB);
    }
}

extern "C" void kernel_launch(void* const* d_in, const int* in_sizes, int n_in,
                              void* d_out, int out_size) {
    const float* X   = (const float*)d_in[0];
    const float* h0  = (const float*)d_in[1];
    const float* W0U = (const float*)d_in[2];
    const float* W0s = (const float*)d_in[3];
    const float* W0V = (const float*)d_in[4];
    const float* WsU = (const float*)d_in[5];
    const float* Wss = (const float*)d_in[6];
    const float* WsV = (const float*)d_in[7];
    float* out = (float*)d_out;

    const int smem_bytes = (2*64*36 + 2*2*32*68) * 4;   // 53248
    static int attr_done = 0;
    if (!attr_done) {
        cudaFuncSetAttribute(rnn_persist,
            cudaFuncAttributeMaxDynamicSharedMemorySize, smem_bytes);
        attr_done = 1;
    }

    dim3 thr(256);
    fuse_mma<<<dim3(27,14,1), thr>>>(0, W0U, W0s, W0V);
    fuse_mma<<<dim3(27,7,8),  thr>>>(1, WsU, Wss, WsV);
    xw_mma<<<dim3(27,256,1), thr>>>(X);
    rnn_persist<<<148, thr, smem_bytes>>>(h0, out);
}